// round 1
// baseline (speedup 1.0000x reference)
#include <cuda_runtime.h>
#include <cstdint>

#define NTOK 49
#define DIM  384
#define NH   12
#define HD   32
#define NWIN 64
#define NBLK 8192
#define SCALE 0.17677669529663687f  /* 1/sqrt(32) */

// smem layout (float offsets)
#define XS_OFF   0        /* [49][388] */
#define OUT_OFF  19012    /* [49][388] */
#define WST_OFF  38024    /* [96][132], aliased by SS [64][60] */
#define SS_OFF   38024
#define QS_OFF   50696    /* [64][36] */
#define KS_OFF   53000    /* [64][36] */
#define VS_OFF   55304    /* [64][40] */
#define SMEM_FLOATS 57864
#define SMEM_BYTES (SMEM_FLOATS * 4)  /* 231456 <= 232448 */

// Precomputed bias+mask table: [NWIN][NH][49][49]
__device__ float g_bm[NWIN * NH * NTOK * NTOK];

__device__ __forceinline__ uint32_t f2tf32u(float x) {
    uint32_t r;
    asm("cvt.rna.tf32.f32 %0, %1;" : "=r"(r) : "f"(x));
    return r;
}
__device__ __forceinline__ float f2tf(float x) { return __uint_as_float(f2tf32u(x)); }

__device__ __forceinline__ void mma8(float* c, uint32_t a0, uint32_t a1, uint32_t a2,
                                     uint32_t a3, uint32_t b0, uint32_t b1) {
    asm volatile(
        "mma.sync.aligned.m16n8k8.row.col.f32.tf32.tf32.f32 "
        "{%0,%1,%2,%3},{%4,%5,%6,%7},{%8,%9},{%0,%1,%2,%3};"
        : "+f"(c[0]), "+f"(c[1]), "+f"(c[2]), "+f"(c[3])
        : "r"(a0), "r"(a1), "r"(a2), "r"(a3), "r"(b0), "r"(b1));
}

__global__ void winattn_prep(const float* __restrict__ mask,
                             const float* __restrict__ table,
                             const int* __restrict__ ridx) {
    const int wv = blockIdx.x;   // window type 0..63
    const int h  = blockIdx.y;   // head
    float* dst = g_bm + (size_t)(wv * NH + h) * (NTOK * NTOK);
    for (int i = threadIdx.x; i < NTOK * NTOK; i += blockDim.x) {
        dst[i] = table[ridx[i] * NH + h] + mask[wv * (NTOK * NTOK) + i];
    }
}

__global__ __launch_bounds__(256, 1)
void winattn_main(const float* __restrict__ x,
                  const float* __restrict__ qkv_w,
                  const float* __restrict__ qkv_b,
                  const float* __restrict__ proj_w,
                  const float* __restrict__ proj_b,
                  float* __restrict__ out) {
    extern __shared__ float sm[];
    const int b    = blockIdx.x;
    const int wi   = b & (NWIN - 1);
    const int tid  = threadIdx.x;
    const int warp = tid >> 5;
    const int lane = tid & 31;
    const int lg   = lane >> 2;   // mma groupID
    const int lt   = lane & 3;    // mma tid-in-group
    const int mt   = warp & 3;    // m-tile (rows mt*16 .. mt*16+15)
    const int nhf  = warp >> 2;   // n-half
    const int r0   = mt * 16 + lg;
    const int r1   = r0 + 8;
    const bool ok0 = r0 < NTOK;
    const bool ok1 = r1 < NTOK;

    // ---- load x (tf32-rounded) into smem ----
    {
        const float4* xg = reinterpret_cast<const float4*>(x + (size_t)b * (NTOK * DIM));
        for (int i = tid; i < NTOK * (DIM / 4); i += 256) {
            int r = i / 96, c4 = i % 96;
            float4 v = xg[i];
            float* d = &sm[XS_OFF + r * 388 + c4 * 4];
            d[0] = f2tf(v.x); d[1] = f2tf(v.y); d[2] = f2tf(v.z); d[3] = f2tf(v.w);
        }
    }

    // ===================== per-head loop =====================
    for (int h = 0; h < NH; h++) {
        // ---- QKV GEMM: (49x384) @ (384x96)^T, staged in 3 K-chunks ----
        float acc[6][4];
        #pragma unroll
        for (int i = 0; i < 6; i++)
            #pragma unroll
            for (int j = 0; j < 4; j++) acc[i][j] = 0.f;

        #pragma unroll 1
        for (int ch = 0; ch < 3; ch++) {
            __syncthreads();   // protect wst (prev chunk mma / prev head ss use)
            const int kc = ch * 128;
            for (int i = tid; i < 96 * 32; i += 256) {
                int j = i >> 5, c4 = i & 31;
                int f = (j >> 5) * 384 + h * 32 + (j & 31);
                float4 v = *reinterpret_cast<const float4*>(qkv_w + (size_t)f * 384 + kc + c4 * 4);
                float* d = &sm[WST_OFF + j * 132 + c4 * 4];
                d[0] = f2tf(v.x); d[1] = f2tf(v.y); d[2] = f2tf(v.z); d[3] = f2tf(v.w);
            }
            __syncthreads();
            #pragma unroll 4
            for (int ks = 0; ks < 16; ks++) {
                const int k0 = kc + ks * 8;
                uint32_t a0 = ok0 ? __float_as_uint(sm[XS_OFF + r0 * 388 + k0 + lt]) : 0u;
                uint32_t a1 = ok1 ? __float_as_uint(sm[XS_OFF + r1 * 388 + k0 + lt]) : 0u;
                uint32_t a2 = ok0 ? __float_as_uint(sm[XS_OFF + r0 * 388 + k0 + 4 + lt]) : 0u;
                uint32_t a3 = ok1 ? __float_as_uint(sm[XS_OFF + r1 * 388 + k0 + 4 + lt]) : 0u;
                #pragma unroll
                for (int nt = 0; nt < 6; nt++) {
                    int n = nhf * 48 + nt * 8 + lg;
                    uint32_t b0 = __float_as_uint(sm[WST_OFF + n * 132 + ks * 8 + lt]);
                    uint32_t b1 = __float_as_uint(sm[WST_OFF + n * 132 + ks * 8 + 4 + lt]);
                    mma8(acc[nt], a0, a1, a2, a3, b0, b1);
                }
            }
        }

        // ---- epilogue: + bias, scale q, round to tf32, scatter to q/k/v ----
        #pragma unroll
        for (int nt = 0; nt < 6; nt++) {
            #pragma unroll
            for (int ci = 0; ci < 4; ci++) {
                int rr = (ci & 2) ? r1 : r0;
                int cc = nhf * 48 + nt * 8 + lt * 2 + (ci & 1);
                int part = cc >> 5, c32 = cc & 31;
                float v = acc[nt][ci] + __ldg(&qkv_b[part * 384 + h * 32 + c32]);
                if (part == 0) v *= SCALE;
                float tv = (rr < NTOK) ? f2tf(v) : 0.f;   // zero-pad rows >= 49
                int off    = (part == 0) ? QS_OFF : (part == 1) ? KS_OFF : VS_OFF;
                int stride = (part == 2) ? 40 : 36;
                sm[off + rr * stride + c32] = tv;
            }
        }
        __syncthreads();

        // ---- S = q @ k^T  (64 x 56, K=32) ----
        float sacc[4][4];
        #pragma unroll
        for (int i = 0; i < 4; i++)
            #pragma unroll
            for (int j = 0; j < 4; j++) sacc[i][j] = 0.f;
        const int nts = (warp < 4) ? 4 : 3;
        const int nbs = (warp < 4) ? 0 : 32;
        #pragma unroll
        for (int ks = 0; ks < 4; ks++) {
            int k0 = ks * 8;
            uint32_t a0 = __float_as_uint(sm[QS_OFF + r0 * 36 + k0 + lt]);
            uint32_t a1 = __float_as_uint(sm[QS_OFF + r1 * 36 + k0 + lt]);
            uint32_t a2 = __float_as_uint(sm[QS_OFF + r0 * 36 + k0 + 4 + lt]);
            uint32_t a3 = __float_as_uint(sm[QS_OFF + r1 * 36 + k0 + 4 + lt]);
            #pragma unroll
            for (int nt = 0; nt < 4; nt++) {
                if (nt < nts) {
                    int n = nbs + nt * 8 + lg;
                    uint32_t b0 = __float_as_uint(sm[KS_OFF + n * 36 + k0 + lt]);
                    uint32_t b1 = __float_as_uint(sm[KS_OFF + n * 36 + k0 + 4 + lt]);
                    mma8(sacc[nt], a0, a1, a2, a3, b0, b1);
                }
            }
        }
        // write S + (rel-pos bias + shift mask) into ss (aliases wst)
        {
            const float* bmh = g_bm + (size_t)(wi * NH + h) * (NTOK * NTOK);
            #pragma unroll
            for (int nt = 0; nt < 4; nt++) {
                if (nt < nts) {
                    #pragma unroll
                    for (int ci = 0; ci < 4; ci++) {
                        int rr = (ci & 2) ? r1 : r0;
                        int cc = nbs + nt * 8 + lt * 2 + (ci & 1);
                        float v = sacc[nt][ci];
                        if (rr < NTOK && cc < NTOK) v += bmh[rr * NTOK + cc];
                        sm[SS_OFF + rr * 60 + cc] = v;
                    }
                }
            }
        }
        __syncthreads();

        // ---- softmax (rows 0..48), write P as tf32, zero pad region ----
        for (int r = warp; r < NTOK; r += 8) {
            float v0 = sm[SS_OFF + r * 60 + lane];
            float v1 = (lane + 32 < NTOK) ? sm[SS_OFF + r * 60 + lane + 32] : -1e30f;
            float mx = fmaxf(v0, v1);
            #pragma unroll
            for (int o = 16; o > 0; o >>= 1) mx = fmaxf(mx, __shfl_xor_sync(0xffffffffu, mx, o));
            float e0 = __expf(v0 - mx);
            float e1 = (lane + 32 < NTOK) ? __expf(v1 - mx) : 0.f;
            float s = e0 + e1;
            #pragma unroll
            for (int o = 16; o > 0; o >>= 1) s += __shfl_xor_sync(0xffffffffu, s, o);
            float inv = 1.0f / s;
            sm[SS_OFF + r * 60 + lane] = f2tf(e0 * inv);
            if (lane + 32 < 56)
                sm[SS_OFF + r * 60 + lane + 32] = (lane + 32 < NTOK) ? f2tf(e1 * inv) : 0.f;
        }
        for (int i = tid; i < 15 * 60; i += 256)   // zero rows 49..63
            sm[SS_OFF + (NTOK + i / 60) * 60 + (i % 60)] = 0.f;
        __syncthreads();

        // ---- O = P @ V  (64 x 32, K=56) ----
        float oacc[2][4];
        #pragma unroll
        for (int i = 0; i < 2; i++)
            #pragma unroll
            for (int j = 0; j < 4; j++) oacc[i][j] = 0.f;
        const int nbo = nhf * 16;
        #pragma unroll
        for (int ks = 0; ks < 7; ks++) {
            int k0 = ks * 8;
            uint32_t a0 = __float_as_uint(sm[SS_OFF + r0 * 60 + k0 + lt]);
            uint32_t a1 = __float_as_uint(sm[SS_OFF + r1 * 60 + k0 + lt]);
            uint32_t a2 = __float_as_uint(sm[SS_OFF + r0 * 60 + k0 + 4 + lt]);
            uint32_t a3 = __float_as_uint(sm[SS_OFF + r1 * 60 + k0 + 4 + lt]);
            #pragma unroll
            for (int nt = 0; nt < 2; nt++) {
                int n = nbo + nt * 8 + lg;
                uint32_t b0 = __float_as_uint(sm[VS_OFF + (k0 + lt) * 40 + n]);
                uint32_t b1 = __float_as_uint(sm[VS_OFF + (k0 + 4 + lt) * 40 + n]);
                mma8(oacc[nt], a0, a1, a2, a3, b0, b1);
            }
        }
        #pragma unroll
        for (int nt = 0; nt < 2; nt++) {
            #pragma unroll
            for (int ci = 0; ci < 4; ci++) {
                int rr = (ci & 2) ? r1 : r0;
                if (rr < NTOK) {
                    int cc = nbo + nt * 8 + lt * 2 + (ci & 1);
                    sm[OUT_OFF + rr * 388 + h * 32 + cc] = f2tf(oacc[nt][ci]);
                }
            }
        }
    } // heads

    // ===================== projection: (49x384) @ (384x384)^T =====================
    #pragma unroll 1
    for (int p = 0; p < 4; p++) {
        float pacc[6][4];
        #pragma unroll
        for (int i = 0; i < 6; i++)
            #pragma unroll
            for (int j = 0; j < 4; j++) pacc[i][j] = 0.f;
        #pragma unroll 1
        for (int ch = 0; ch < 3; ch++) {
            __syncthreads();
            const int kc = ch * 128;
            for (int i = tid; i < 96 * 32; i += 256) {
                int j = i >> 5, c4 = i & 31;
                float4 v = *reinterpret_cast<const float4*>(
                    proj_w + (size_t)(p * 96 + j) * 384 + kc + c4 * 4);
                float* d = &sm[WST_OFF + j * 132 + c4 * 4];
                d[0] = f2tf(v.x); d[1] = f2tf(v.y); d[2] = f2tf(v.z); d[3] = f2tf(v.w);
            }
            __syncthreads();
            #pragma unroll 4
            for (int ks = 0; ks < 16; ks++) {
                const int k0 = kc + ks * 8;
                uint32_t a0 = ok0 ? __float_as_uint(sm[OUT_OFF + r0 * 388 + k0 + lt]) : 0u;
                uint32_t a1 = ok1 ? __float_as_uint(sm[OUT_OFF + r1 * 388 + k0 + lt]) : 0u;
                uint32_t a2 = ok0 ? __float_as_uint(sm[OUT_OFF + r0 * 388 + k0 + 4 + lt]) : 0u;
                uint32_t a3 = ok1 ? __float_as_uint(sm[OUT_OFF + r1 * 388 + k0 + 4 + lt]) : 0u;
                #pragma unroll
                for (int nt = 0; nt < 6; nt++) {
                    int n = nhf * 48 + nt * 8 + lg;
                    uint32_t b0 = __float_as_uint(sm[WST_OFF + n * 132 + ks * 8 + lt]);
                    uint32_t b1 = __float_as_uint(sm[WST_OFF + n * 132 + ks * 8 + 4 + lt]);
                    mma8(pacc[nt], a0, a1, a2, a3, b0, b1);
                }
            }
        }
        float* og = out + (size_t)b * (NTOK * DIM);
        #pragma unroll
        for (int nt = 0; nt < 6; nt++) {
            #pragma unroll
            for (int ci = 0; ci < 4; ci++) {
                int rr = (ci & 2) ? r1 : r0;
                if (rr < NTOK) {
                    int cc = p * 96 + nhf * 48 + nt * 8 + lt * 2 + (ci & 1);
                    og[rr * 384 + cc] = pacc[nt][ci] + __ldg(&proj_b[cc]);
                }
            }
        }
    }
}

extern "C" void kernel_launch(void* const* d_in, const int* in_sizes, int n_in,
                              void* d_out, int out_size) {
    const float* x      = (const float*)d_in[0];
    const float* mask   = (const float*)d_in[1];
    const float* table  = (const float*)d_in[2];
    const float* qkv_w  = (const float*)d_in[3];
    const float* qkv_b  = (const float*)d_in[4];
    const float* proj_w = (const float*)d_in[5];
    const float* proj_b = (const float*)d_in[6];
    const int*   ridx   = (const int*)d_in[7];
    float* out = (float*)d_out;

    cudaFuncSetAttribute(winattn_main, cudaFuncAttributeMaxDynamicSharedMemorySize, SMEM_BYTES);

    winattn_prep<<<dim3(NWIN, NH), 128>>>(mask, table, ridx);
    winattn_main<<<NBLK, 256, SMEM_BYTES>>>(x, qkv_w, qkv_b, proj_w, proj_b, out);
}

// round 2
// speedup vs baseline: 1.0358x; 1.0358x over previous
#include <cuda_runtime.h>
#include <cstdint>

#define NTOK 49
#define DIM  384
#define NH   12
#define NWIN 64
#define NBLK 8192
#define NTHR 384
#define SCALE 0.17677669529663687f  /* 1/sqrt(32) */

// smem float offsets
#define XP_OFF   0            /* packed X     [49][384]  (fragment order, swizzled) */
#define OUTP_OFF 18816        /* packed O     [49][384]  */
#define WP_OFF   37632        /* packed W chunk [96][128] (aliased by SS/SP)        */
#define SS_OFF   37632        /* plain S      [64][60]   */
#define SP_OFF   41472        /* packed P     [64][56]   */
#define QP_OFF   49920        /* packed Q     [49][32]   */
#define KP_OFF   51488        /* packed K     [56][32]   */
#define VT_OFF   53280        /* packed V^T   [32][56]   */
#define SMEM_FLOATS 55072
#define SMEM_BYTES (SMEM_FLOATS * 4)   /* 220288 */

__device__ float g_bm[NWIN * NH * NTOK * NTOK];

__device__ __forceinline__ uint32_t f2tf32u(float x) {
    uint32_t r;
    asm("cvt.rna.tf32.f32 %0, %1;" : "=r"(r) : "f"(x));
    return r;
}
__device__ __forceinline__ float f2tf(float x) { return __uint_as_float(f2tf32u(x)); }

__device__ __forceinline__ void mma8(float* c, uint32_t a0, uint32_t a1, uint32_t a2,
                                     uint32_t a3, uint32_t b0, uint32_t b1) {
    asm volatile(
        "mma.sync.aligned.m16n8k8.row.col.f32.tf32.tf32.f32 "
        "{%0,%1,%2,%3},{%4,%5,%6,%7},{%8,%9},{%0,%1,%2,%3};"
        : "+f"(c[0]), "+f"(c[1]), "+f"(c[2]), "+f"(c[3])
        : "r"(a0), "r"(a1), "r"(a2), "r"(a3), "r"(b0), "r"(b1));
}
#define U(x) __float_as_uint(x)

__global__ void winattn_prep(const float* __restrict__ mask,
                             const float* __restrict__ table,
                             const int* __restrict__ ridx) {
    const int wv = blockIdx.x;
    const int h  = blockIdx.y;
    float* dst = g_bm + (size_t)(wv * NH + h) * (NTOK * NTOK);
    for (int i = threadIdx.x; i < NTOK * NTOK; i += blockDim.x) {
        dst[i] = table[ridx[i] * NH + h] + mask[wv * (NTOK * NTOK) + i];
    }
}

__global__ __launch_bounds__(NTHR, 1)
void winattn_main(const float* __restrict__ x,
                  const float* __restrict__ qkv_w,
                  const float* __restrict__ qkv_b,
                  const float* __restrict__ proj_w,
                  const float* __restrict__ proj_b,
                  float* __restrict__ out) {
    extern __shared__ float sm[];
    const int b    = blockIdx.x;
    const int wi   = b & (NWIN - 1);
    const int tid  = threadIdx.x;
    const int warp = tid >> 5;
    const int lane = tid & 31;
    const int lg   = lane >> 2;
    const int lt   = lane & 3;
    const int mt   = warp & 3;      // m-tile
    const int ng   = warp >> 2;     // column group 0..2
    const int r0   = mt * 16 + lg;
    const int r1   = r0 + 8;
    const bool ok0 = r0 < NTOK;
    const bool ok1 = r1 < NTOK;

    // ---- stage X into fragment-packed layout ----
    {
        const float4* xg = reinterpret_cast<const float4*>(x + (size_t)b * (NTOK * DIM));
        for (int i = tid; i < NTOK * 96; i += NTHR) {
            int r = i / 96, c4 = i % 96;
            float4 v = xg[i];
            int g = c4 >> 2, s = c4 & 3;
            float* d = &sm[XP_OFF + r * 384 + ((g ^ (r & 1)) << 4) + s];
            d[0] = f2tf(v.x); d[4] = f2tf(v.y); d[8] = f2tf(v.z); d[12] = f2tf(v.w);
        }
    }

    // ===================== per-head =====================
    #pragma unroll 1
    for (int h = 0; h < NH; h++) {
        // ---- QKV GEMM (64x96, K=384 in 3 chunks). warp -> (mt, 4 nt in group ng) ----
        float acc[4][4];
        #pragma unroll
        for (int i = 0; i < 4; i++)
            #pragma unroll
            for (int j = 0; j < 4; j++) acc[i][j] = 0.f;

        #pragma unroll 1
        for (int ch = 0; ch < 3; ch++) {
            __syncthreads();
            for (int i = tid; i < 96 * 32; i += NTHR) {
                int n = i >> 5, c4 = i & 31;
                int f = (n >> 5) * 384 + h * 32 + (n & 31);
                float4 v = *reinterpret_cast<const float4*>(
                    qkv_w + (size_t)f * 384 + ch * 128 + c4 * 4);
                int g = c4 >> 2, s = c4 & 3;
                float* d = &sm[WP_OFF + n * 128 + ((g ^ (n & 1)) << 4) + s];
                d[0] = f2tf(v.x); d[4] = f2tf(v.y); d[8] = f2tf(v.z); d[12] = f2tf(v.w);
            }
            __syncthreads();
            #pragma unroll
            for (int gl = 0; gl < 8; gl++) {
                const int gx = ch * 8 + gl;
                float4 A0 = make_float4(0.f, 0.f, 0.f, 0.f), A1 = A0;
                if (ok0) A0 = *reinterpret_cast<const float4*>(
                    &sm[XP_OFF + r0 * 384 + ((gx ^ (r0 & 1)) << 4) + (lt << 2)]);
                if (ok1) A1 = *reinterpret_cast<const float4*>(
                    &sm[XP_OFF + r1 * 384 + ((gx ^ (r1 & 1)) << 4) + (lt << 2)]);
                #pragma unroll
                for (int ntl = 0; ntl < 4; ntl++) {
                    int n = ng * 32 + ntl * 8 + lg;
                    float4 B = *reinterpret_cast<const float4*>(
                        &sm[WP_OFF + n * 128 + ((gl ^ (n & 1)) << 4) + (lt << 2)]);
                    mma8(acc[ntl], U(A0.x), U(A1.x), U(A0.y), U(A1.y), U(B.x), U(B.y));
                    mma8(acc[ntl], U(A0.z), U(A1.z), U(A0.w), U(A1.w), U(B.z), U(B.w));
                }
            }
        }

        // ---- epilogue: warp group ng==0 -> Q (scaled), 1 -> K, 2 -> V ----
        #pragma unroll
        for (int ntl = 0; ntl < 4; ntl++) {
            #pragma unroll
            for (int ci = 0; ci < 4; ci++) {
                int rr  = (ci & 2) ? r1 : r0;
                int c32 = ntl * 8 + (lt << 1) + (ci & 1);
                float v = acc[ntl][ci] + __ldg(&qkv_b[ng * 384 + h * 32 + c32]);
                if (ng == 0) {
                    if (rr < NTOK) {
                        v *= SCALE;
                        int pos = rr * 32 + (((c32 >> 3) ^ (rr & 3)) << 3)
                                + ((c32 & 3) << 1) + ((c32 >> 2) & 1);
                        sm[QP_OFF + pos] = f2tf(v);
                    }
                } else if (ng == 1) {
                    if (rr < 56) {
                        int pos = rr * 32 + (((c32 >> 3) ^ (rr & 3)) << 3)
                                + ((c32 & 3) << 1) + ((c32 >> 2) & 1);
                        sm[KP_OFF + pos] = f2tf(v);
                    }
                } else {
                    if (rr < 56) {
                        int pos = c32 * 56 + ((rr >> 3) << 3) + ((rr & 3) << 1) + ((rr >> 2) & 1);
                        sm[VT_OFF + pos] = f2tf(v);
                    }
                }
            }
        }
        __syncthreads();

        // ---- S = q @ k^T (64x56, K=32). warp -> (mt, nt set) ----
        {
            float sacc[3][4];
            #pragma unroll
            for (int i = 0; i < 3; i++)
                #pragma unroll
                for (int j = 0; j < 4; j++) sacc[i][j] = 0.f;
            const int ntn = (ng == 2) ? 3 : 2;
            const int ntb = (ng == 2) ? 4 : ng * 2;
            #pragma unroll
            for (int ks = 0; ks < 4; ks++) {
                float2 A0 = make_float2(0.f, 0.f), A1 = A0;
                if (ok0) A0 = *reinterpret_cast<const float2*>(
                    &sm[QP_OFF + r0 * 32 + ((ks ^ (r0 & 3)) << 3) + (lt << 1)]);
                if (ok1) A1 = *reinterpret_cast<const float2*>(
                    &sm[QP_OFF + r1 * 32 + ((ks ^ (r1 & 3)) << 3) + (lt << 1)]);
                #pragma unroll
                for (int j = 0; j < 3; j++) {
                    if (j < ntn) {
                        int n = (ntb + j) * 8 + lg;
                        float2 B = *reinterpret_cast<const float2*>(
                            &sm[KP_OFF + n * 32 + ((ks ^ (n & 3)) << 3) + (lt << 1)]);
                        mma8(sacc[j], U(A0.x), U(A1.x), U(A0.y), U(A1.y), U(B.x), U(B.y));
                    }
                }
            }
            const float* bmh = g_bm + (size_t)(wi * NH + h) * (NTOK * NTOK);
            #pragma unroll
            for (int j = 0; j < 3; j++) {
                if (j < ntn) {
                    #pragma unroll
                    for (int ci = 0; ci < 4; ci++) {
                        int rr = (ci & 2) ? r1 : r0;
                        int cc = (ntb + j) * 8 + (lt << 1) + (ci & 1);
                        float v = sacc[j][ci];
                        if (rr < NTOK && cc < NTOK) v += bmh[rr * NTOK + cc];
                        sm[SS_OFF + rr * 60 + cc] = v;
                    }
                }
            }
        }
        __syncthreads();

        // ---- softmax rows 0..48, write packed P; zero pad rows ----
        for (int r = warp; r < NTOK; r += 12) {
            float v0 = sm[SS_OFF + r * 60 + lane];
            float v1 = (lane + 32 < NTOK) ? sm[SS_OFF + r * 60 + lane + 32] : -1e30f;
            float mx = fmaxf(v0, v1);
            #pragma unroll
            for (int o = 16; o > 0; o >>= 1) mx = fmaxf(mx, __shfl_xor_sync(0xffffffffu, mx, o));
            float e0 = __expf(v0 - mx);
            float e1 = (lane + 32 < NTOK) ? __expf(v1 - mx) : 0.f;
            float s = e0 + e1;
            #pragma unroll
            for (int o = 16; o > 0; o >>= 1) s += __shfl_xor_sync(0xffffffffu, s, o);
            float inv = 1.0f / s;
            int c = lane;
            sm[SP_OFF + r * 56 + ((c >> 3) << 3) + ((c & 3) << 1) + ((c >> 2) & 1)] = f2tf(e0 * inv);
            int c2 = lane + 32;
            if (c2 < 56) {
                float pv = (c2 < NTOK) ? f2tf(e1 * inv) : 0.f;
                sm[SP_OFF + r * 56 + ((c2 >> 3) << 3) + ((c2 & 3) << 1) + ((c2 >> 2) & 1)] = pv;
            }
        }
        for (int i = tid; i < 15 * 56; i += NTHR)
            sm[SP_OFF + NTOK * 56 + i] = 0.f;
        __syncthreads();

        // ---- O = P @ V (64x32, K=56) ----
        {
            float oacc[2][4];
            #pragma unroll
            for (int i = 0; i < 2; i++)
                #pragma unroll
                for (int j = 0; j < 4; j++) oacc[i][j] = 0.f;
            const int non = (ng == 2) ? 2 : 1;
            const int nob = (ng == 2) ? 2 : ng;
            #pragma unroll
            for (int ks = 0; ks < 7; ks++) {
                float2 A0 = *reinterpret_cast<const float2*>(
                    &sm[SP_OFF + r0 * 56 + (ks << 3) + (lt << 1)]);
                float2 A1 = *reinterpret_cast<const float2*>(
                    &sm[SP_OFF + r1 * 56 + (ks << 3) + (lt << 1)]);
                #pragma unroll
                for (int j = 0; j < 2; j++) {
                    if (j < non) {
                        int n = (nob + j) * 8 + lg;
                        float2 B = *reinterpret_cast<const float2*>(
                            &sm[VT_OFF + n * 56 + (ks << 3) + (lt << 1)]);
                        mma8(oacc[j], U(A0.x), U(A1.x), U(A0.y), U(A1.y), U(B.x), U(B.y));
                    }
                }
            }
            #pragma unroll
            for (int j = 0; j < 2; j++) {
                if (j < non) {
                    #pragma unroll
                    for (int ci = 0; ci < 4; ci++) {
                        int rr = (ci & 2) ? r1 : r0;
                        if (rr < NTOK) {
                            int cc = (nob + j) * 8 + (lt << 1) + (ci & 1);
                            int oc = h * 32 + cc;
                            int go = oc >> 4;
                            int pos = rr * 384 + ((go ^ (rr & 1)) << 4)
                                    + ((oc & 3) << 2) + ((oc >> 2) & 3);
                            sm[OUTP_OFF + pos] = f2tf(oacc[j][ci]);
                        }
                    }
                }
            }
        }
    } // heads

    // ===================== projection (49x384 @ 384x384^T) =====================
    #pragma unroll 1
    for (int p = 0; p < 4; p++) {
        float pacc[4][4];
        #pragma unroll
        for (int i = 0; i < 4; i++)
            #pragma unroll
            for (int j = 0; j < 4; j++) pacc[i][j] = 0.f;
        #pragma unroll 1
        for (int ch = 0; ch < 3; ch++) {
            __syncthreads();
            for (int i = tid; i < 96 * 32; i += NTHR) {
                int n = i >> 5, c4 = i & 31;
                float4 v = *reinterpret_cast<const float4*>(
                    proj_w + (size_t)(p * 96 + n) * 384 + ch * 128 + c4 * 4);
                int g = c4 >> 2, s = c4 & 3;
                float* d = &sm[WP_OFF + n * 128 + ((g ^ (n & 1)) << 4) + s];
                d[0] = f2tf(v.x); d[4] = f2tf(v.y); d[8] = f2tf(v.z); d[12] = f2tf(v.w);
            }
            __syncthreads();
            #pragma unroll
            for (int gl = 0; gl < 8; gl++) {
                const int gx = ch * 8 + gl;
                float4 A0 = make_float4(0.f, 0.f, 0.f, 0.f), A1 = A0;
                if (ok0) A0 = *reinterpret_cast<const float4*>(
                    &sm[OUTP_OFF + r0 * 384 + ((gx ^ (r0 & 1)) << 4) + (lt << 2)]);
                if (ok1) A1 = *reinterpret_cast<const float4*>(
                    &sm[OUTP_OFF + r1 * 384 + ((gx ^ (r1 & 1)) << 4) + (lt << 2)]);
                #pragma unroll
                for (int ntl = 0; ntl < 4; ntl++) {
                    int n = ng * 32 + ntl * 8 + lg;
                    float4 B = *reinterpret_cast<const float4*>(
                        &sm[WP_OFF + n * 128 + ((gl ^ (n & 1)) << 4) + (lt << 2)]);
                    mma8(pacc[ntl], U(A0.x), U(A1.x), U(A0.y), U(A1.y), U(B.x), U(B.y));
                    mma8(pacc[ntl], U(A0.z), U(A1.z), U(A0.w), U(A1.w), U(B.z), U(B.w));
                }
            }
        }
        float* og = out + (size_t)b * (NTOK * DIM);
        #pragma unroll
        for (int ntl = 0; ntl < 4; ntl++) {
            #pragma unroll
            for (int ci = 0; ci < 4; ci++) {
                int rr = (ci & 2) ? r1 : r0;
                if (rr < NTOK) {
                    int cc = p * 96 + ng * 32 + ntl * 8 + (lt << 1) + (ci & 1);
                    og[rr * 384 + cc] = pacc[ntl][ci] + __ldg(&proj_b[cc]);
                }
            }
        }
    }
}

extern "C" void kernel_launch(void* const* d_in, const int* in_sizes, int n_in,
                              void* d_out, int out_size) {
    const float* x      = (const float*)d_in[0];
    const float* mask   = (const float*)d_in[1];
    const float* table  = (const float*)d_in[2];
    const float* qkv_w  = (const float*)d_in[3];
    const float* qkv_b  = (const float*)d_in[4];
    const float* proj_w = (const float*)d_in[5];
    const float* proj_b = (const float*)d_in[6];
    const int*   ridx   = (const int*)d_in[7];
    float* out = (float*)d_out;

    cudaFuncSetAttribute(winattn_main, cudaFuncAttributeMaxDynamicSharedMemorySize, SMEM_BYTES);

    winattn_prep<<<dim3(NWIN, NH), 128>>>(mask, table, ridx);
    winattn_main<<<NBLK, NTHR, SMEM_BYTES>>>(x, qkv_w, qkv_b, proj_w, proj_b, out);
}

// round 4
// speedup vs baseline: 1.6370x; 1.5805x over previous
#include <cuda_runtime.h>
#include <cstdint>

#define NTOK 49
#define NH   12
#define NWIN 64
#define NBLK 8192
#define NROWS (NBLK * NTOK)     /* 401408 = 3136 * 128 */
#define NMT  3136
#define SCALE 0.17677669529663687f

/* gemm smem: A [128][400] floats, then B chunk [192][32] floats */
#define SA   400
#define GSB  (128 * SA)                 /* 51200 float offset */
#define GSMEM_BYTES ((GSB + 6144) * 4)  /* 229376 */

/* ---------------- device scratch (static; no allocs) ---------------- */
__device__ float g_qkv[NROWS * 1152];   /* 1.85GB fp32 */
__device__ float g_obuf[NROWS * 384];   /* 616MB */
__device__ float g_wq[6 * 12 * 6144];   /* qkv_w packed  [nb][kc][192][32] */
__device__ float g_wp[2 * 12 * 6144];   /* proj_w packed */
__device__ float g_bm[NWIN * NH * NTOK * NTOK];

/* ---------------- helpers ---------------- */
__device__ __forceinline__ uint32_t f2tf32u(float x) {
    uint32_t r;
    asm("cvt.rna.tf32.f32 %0, %1;" : "=r"(r) : "f"(x));
    return r;
}
__device__ __forceinline__ float f2tf(float x) { return __uint_as_float(f2tf32u(x)); }

__device__ __forceinline__ void mma8(float* c, uint32_t a0, uint32_t a1, uint32_t a2,
                                     uint32_t a3, uint32_t b0, uint32_t b1) {
    asm volatile(
        "mma.sync.aligned.m16n8k8.row.col.f32.tf32.tf32.f32 "
        "{%0,%1,%2,%3},{%4,%5,%6,%7},{%8,%9},{%0,%1,%2,%3};"
        : "+f"(c[0]), "+f"(c[1]), "+f"(c[2]), "+f"(c[3])
        : "r"(a0), "r"(a1), "r"(a2), "r"(a3), "r"(b0), "r"(b1));
}
#define U(x) __float_as_uint(x)

/* ---------------- prep: pack weights into fragment chunks ----------------
   chunk layout [nb][kc][n in 192][k in 32]:
   pos = n*32 + ((gl ^ (n&1))<<4) + s + 4*j,  gl=k'>>4, s=(k'>>2)&3, j=k'&3 */
__global__ void prep_pack(const float* __restrict__ qkv_w, const float* __restrict__ proj_w) {
    int i = blockIdx.x * 256 + threadIdx.x;
    const float* src;
    float* dst;
    if (i < 1152 * 384) { src = qkv_w; dst = g_wq; }
    else { i -= 1152 * 384; src = proj_w; dst = g_wp; }
    int c = i / 384, k = i - c * 384;
    float v = f2tf(src[(size_t)c * 384 + k]);
    int nb = c / 192, n = c - nb * 192;
    int kc = k >> 5, k1 = k & 31;
    int gl = k1 >> 4, s = (k1 >> 2) & 3, j = k1 & 3;
    int pos = n * 32 + ((gl ^ (n & 1)) << 4) + s + 4 * j;
    dst[(nb * 12 + kc) * 6144 + pos] = v;
}

__global__ void prep_bm(const float* __restrict__ mask, const float* __restrict__ table,
                        const int* __restrict__ ridx) {
    const int wv = blockIdx.x, h = blockIdx.y;
    float* dst = g_bm + (size_t)(wv * NH + h) * (NTOK * NTOK);
    for (int i = threadIdx.x; i < NTOK * NTOK; i += blockDim.x)
        dst[i] = table[ridx[i] * NH + h] + mask[wv * (NTOK * NTOK) + i];
}

/* ---------------- register-blocked tf32 mma.sync GEMM ----------------
   C[128 rows][nbN*192 cols] = A[128][384] @ W^T + bias
   mode 0: A=x, W=g_wq, C=g_qkv (ldc 1152, nbN 6)
   mode 1: A=g_obuf, W=g_wp, C=out (ldc 384, nbN 2)                    */
__global__ __launch_bounds__(256, 1)
void gemm_mm(const float* __restrict__ Aext, const float* __restrict__ bias,
             float* __restrict__ Cext, int ldc, int nbN, int mode) {
    extern __shared__ float sm[];
    float* smA = sm;
    float* smB = sm + GSB;
    const int tid = threadIdx.x, warp = tid >> 5, lane = tid & 31;
    const int lg = lane >> 2, lt = lane & 3;
    const int warpm = warp & 3, warpn = warp >> 2;
    const int mbase = blockIdx.x * 128;

    const float* A = mode ? g_obuf : Aext;
    const float* W = mode ? g_wp : g_wq;
    float* C       = mode ? Cext : g_qkv;

    /* stage A once: 128 x 384, tf32-rounded, fragment order, stride 400 */
    {
        const float* Ab = A + (size_t)mbase * 384;
        for (int i = tid; i < 12288; i += 256) {
            int r = i / 96, c4 = i - r * 96;
            float4 v = *reinterpret_cast<const float4*>(Ab + r * 384 + c4 * 4);
            float* d = &smA[r * SA + ((c4 >> 2) << 4) + (c4 & 3)];
            d[0] = f2tf(v.x); d[4] = f2tf(v.y); d[8] = f2tf(v.z); d[12] = f2tf(v.w);
        }
    }

    #pragma unroll 1
    for (int nb = 0; nb < nbN; nb++) {
        float acc[2][12][4];
        #pragma unroll
        for (int a = 0; a < 2; a++)
            #pragma unroll
            for (int b = 0; b < 12; b++)
                #pragma unroll
                for (int c = 0; c < 4; c++) acc[a][b][c] = 0.f;

        const float* Wnb = W + (size_t)nb * 12 * 6144;
        #pragma unroll 1
        for (int kc = 0; kc < 12; kc++) {
            __syncthreads();
            {
                const float4* s4 = reinterpret_cast<const float4*>(Wnb + kc * 6144);
                float4* d4 = reinterpret_cast<float4*>(smB);
                #pragma unroll
                for (int i = 0; i < 6; i++) d4[tid + i * 256] = s4[tid + i * 256];
            }
            __syncthreads();
            #pragma unroll
            for (int gl = 0; gl < 2; gl++) {
                const int g = kc * 2 + gl;
                const int ra = warpm * 32 + lg;
                const float* ab = &smA[g * 16 + lt * 4];
                float4 a0 = *reinterpret_cast<const float4*>(ab + ra * SA);
                float4 a1 = *reinterpret_cast<const float4*>(ab + (ra + 8) * SA);
                float4 a2 = *reinterpret_cast<const float4*>(ab + (ra + 16) * SA);
                float4 a3 = *reinterpret_cast<const float4*>(ab + (ra + 24) * SA);
                #pragma unroll
                for (int nf = 0; nf < 12; nf++) {
                    int n = warpn * 96 + nf * 8 + lg;
                    float4 bf = *reinterpret_cast<const float4*>(
                        &smB[n * 32 + ((gl ^ (n & 1)) << 4) + lt * 4]);
                    mma8(acc[0][nf], U(a0.x), U(a1.x), U(a0.y), U(a1.y), U(bf.x), U(bf.y));
                    mma8(acc[0][nf], U(a0.z), U(a1.z), U(a0.w), U(a1.w), U(bf.z), U(bf.w));
                    mma8(acc[1][nf], U(a2.x), U(a3.x), U(a2.y), U(a3.y), U(bf.x), U(bf.y));
                    mma8(acc[1][nf], U(a2.z), U(a3.z), U(a2.w), U(a3.w), U(bf.z), U(bf.w));
                }
            }
        }
        /* epilogue: bias add + direct global store */
        const int cb = nb * 192 + warpn * 96;
        #pragma unroll
        for (int nf = 0; nf < 12; nf++) {
            int col = cb + nf * 8 + lt * 2;
            float b0 = __ldg(&bias[col]), b1 = __ldg(&bias[col + 1]);
            #pragma unroll
            for (int mt = 0; mt < 2; mt++) {
                int r = mbase + warpm * 32 + mt * 16 + lg;
                float2 v0 = make_float2(acc[mt][nf][0] + b0, acc[mt][nf][1] + b1);
                float2 v1 = make_float2(acc[mt][nf][2] + b0, acc[mt][nf][3] + b1);
                *reinterpret_cast<float2*>(&C[(size_t)r * ldc + col]) = v0;
                *reinterpret_cast<float2*>(&C[(size_t)(r + 8) * ldc + col]) = v1;
            }
        }
    }
}

/* ---------------- attention kernel (mma.sync, per window) ---------------- */
#define QP_OFF 0
#define KP_OFF 1568
#define VT_OFF 3360
#define SS_OFF 5152
/* total 8992 floats = 35968 B static smem */

__global__ __launch_bounds__(384, 2)
void attn_kernel() {
    __shared__ float sm[8992];
    const int b = blockIdx.x;
    const int wi = b & (NWIN - 1);
    const int tokbase = b * NTOK;
    const int tid = threadIdx.x, warp = tid >> 5, lane = tid & 31;
    const int lg = lane >> 2, lt = lane & 3;
    const int mt = warp & 3, ng = warp >> 2;
    const int r0 = mt * 16 + lg, r1 = r0 + 8;
    const bool ok0 = r0 < NTOK, ok1 = r1 < NTOK;

    for (int i = tid; i < 3584; i += 384) sm[KP_OFF + i] = 0.f;   /* zero KP+VT pads */
    __syncthreads();

    #pragma unroll 1
    for (int h = 0; h < NH; h++) {
        /* stage Q (scaled), K, V head slices from g_qkv */
        for (int i = tid; i < NTOK * 8; i += 384) {
            int r = i >> 3, c4 = i & 7;
            const float* base = g_qkv + (size_t)(tokbase + r) * 1152 + h * 32 + (c4 << 2);
            float4 q  = *reinterpret_cast<const float4*>(base);
            float4 kk = *reinterpret_cast<const float4*>(base + 384);
            float4 vv = *reinterpret_cast<const float4*>(base + 768);
            float qa[4] = {q.x, q.y, q.z, q.w};
            float ka[4] = {kk.x, kk.y, kk.z, kk.w};
            float va[4] = {vv.x, vv.y, vv.z, vv.w};
            #pragma unroll
            for (int d = 0; d < 4; d++) {
                int c32 = (c4 << 2) + d;
                int pp = r * 32 + (((c32 >> 3) ^ (r & 3)) << 3) + ((c32 & 3) << 1) + ((c32 >> 2) & 1);
                sm[QP_OFF + pp] = f2tf(qa[d] * SCALE);
                sm[KP_OFF + pp] = f2tf(ka[d]);
                sm[VT_OFF + c32 * 56 + ((r >> 3) << 3) + ((r & 3) << 1) + ((r >> 2) & 1)] = f2tf(va[d]);
            }
        }
        __syncthreads();

        /* S = q @ k^T (64x56, K=32) + bias+mask, into SS (stride 60) */
        {
            float sacc[3][4];
            #pragma unroll
            for (int i = 0; i < 3; i++)
                #pragma unroll
                for (int j = 0; j < 4; j++) sacc[i][j] = 0.f;
            const int ntn = (ng == 2) ? 3 : 2;
            const int ntb = (ng == 2) ? 4 : ng * 2;
            #pragma unroll
            for (int ks = 0; ks < 4; ks++) {
                float2 A0 = make_float2(0.f, 0.f), A1 = A0;
                if (ok0) A0 = *reinterpret_cast<const float2*>(
                    &sm[QP_OFF + r0 * 32 + ((ks ^ (r0 & 3)) << 3) + (lt << 1)]);
                if (ok1) A1 = *reinterpret_cast<const float2*>(
                    &sm[QP_OFF + r1 * 32 + ((ks ^ (r1 & 3)) << 3) + (lt << 1)]);
                #pragma unroll
                for (int j = 0; j < 3; j++) {
                    if (j < ntn) {
                        int n = (ntb + j) * 8 + lg;
                        float2 B = *reinterpret_cast<const float2*>(
                            &sm[KP_OFF + n * 32 + ((ks ^ (n & 3)) << 3) + (lt << 1)]);
                        mma8(sacc[j], U(A0.x), U(A1.x), U(A0.y), U(A1.y), U(B.x), U(B.y));
                    }
                }
            }
            const float* bmh = g_bm + (size_t)(wi * NH + h) * (NTOK * NTOK);
            #pragma unroll
            for (int j = 0; j < 3; j++) {
                if (j < ntn) {
                    #pragma unroll
                    for (int ci = 0; ci < 4; ci++) {
                        int rr = (ci & 2) ? r1 : r0;
                        int cc = (ntb + j) * 8 + (lt << 1) + (ci & 1);
                        float v = sacc[j][ci];
                        if (rr < NTOK && cc < NTOK) v += bmh[rr * NTOK + cc];
                        sm[SS_OFF + rr * 60 + cc] = v;
                    }
                }
            }
        }
        __syncthreads();

        /* softmax rows 0..48 (write packed P in place), zero pad rows */
        for (int r = warp; r < NTOK; r += 12) {
            float v0 = sm[SS_OFF + r * 60 + lane];
            float v1 = (lane + 32 < NTOK) ? sm[SS_OFF + r * 60 + lane + 32] : -1e30f;
            float mx = fmaxf(v0, v1);
            #pragma unroll
            for (int o = 16; o > 0; o >>= 1) mx = fmaxf(mx, __shfl_xor_sync(0xffffffffu, mx, o));
            float e0 = __expf(v0 - mx);
            float e1 = (lane + 32 < NTOK) ? __expf(v1 - mx) : 0.f;
            float s = e0 + e1;
            #pragma unroll
            for (int o = 16; o > 0; o >>= 1) s += __shfl_xor_sync(0xffffffffu, s, o);
            float inv = 1.0f / s;
            int c = lane;
            sm[SS_OFF + r * 60 + ((c >> 3) << 3) + ((c & 3) << 1) + ((c >> 2) & 1)] = f2tf(e0 * inv);
            int c2 = lane + 32;
            if (c2 < 56) {
                float pv = (c2 < NTOK) ? f2tf(e1 * inv) : 0.f;
                sm[SS_OFF + r * 60 + ((c2 >> 3) << 3) + ((c2 & 3) << 1) + ((c2 >> 2) & 1)] = pv;
            }
        }
        for (int i = tid; i < 15 * 60; i += 384)
            sm[SS_OFF + NTOK * 60 + i] = 0.f;
        __syncthreads();

        /* O = P @ V (64x32, K=56) -> g_obuf */
        {
            float oacc[2][4];
            #pragma unroll
            for (int i = 0; i < 2; i++)
                #pragma unroll
                for (int j = 0; j < 4; j++) oacc[i][j] = 0.f;
            const int non = (ng == 2) ? 2 : 1;
            const int nob = (ng == 2) ? 2 : ng;
            #pragma unroll
            for (int ks = 0; ks < 7; ks++) {
                float2 A0 = *reinterpret_cast<const float2*>(
                    &sm[SS_OFF + r0 * 60 + (ks << 3) + (lt << 1)]);
                float2 A1 = *reinterpret_cast<const float2*>(
                    &sm[SS_OFF + r1 * 60 + (ks << 3) + (lt << 1)]);
                #pragma unroll
                for (int j = 0; j < 2; j++) {
                    if (j < non) {
                        int n = (nob + j) * 8 + lg;
                        float2 B = *reinterpret_cast<const float2*>(
                            &sm[VT_OFF + n * 56 + (ks << 3) + (lt << 1)]);
                        mma8(oacc[j], U(A0.x), U(A1.x), U(A0.y), U(A1.y), U(B.x), U(B.y));
                    }
                }
            }
            #pragma unroll
            for (int j = 0; j < 2; j++) {
                if (j < non) {
                    #pragma unroll
                    for (int ci = 0; ci < 4; ci++) {
                        int rr = (ci & 2) ? r1 : r0;
                        if (rr < NTOK) {
                            int cc = (nob + j) * 8 + (lt << 1) + (ci & 1);
                            g_obuf[(size_t)(tokbase + rr) * 384 + h * 32 + cc] = oacc[j][ci];
                        }
                    }
                }
            }
        }
        __syncthreads();
    }
}

/* ---------------- launcher ---------------- */
extern "C" void kernel_launch(void* const* d_in, const int* in_sizes, int n_in,
                              void* d_out, int out_size) {
    const float* x      = (const float*)d_in[0];
    const float* mask   = (const float*)d_in[1];
    const float* table  = (const float*)d_in[2];
    const float* qkv_w  = (const float*)d_in[3];
    const float* qkv_b  = (const float*)d_in[4];
    const float* proj_w = (const float*)d_in[5];
    const float* proj_b = (const float*)d_in[6];
    const int*   ridx   = (const int*)d_in[7];
    float* out = (float*)d_out;

    cudaFuncSetAttribute(gemm_mm, cudaFuncAttributeMaxDynamicSharedMemorySize, GSMEM_BYTES);

    prep_pack<<<2304, 256>>>(qkv_w, proj_w);
    prep_bm<<<dim3(NWIN, NH), 128>>>(mask, table, ridx);
    gemm_mm<<<NMT, 256, GSMEM_BYTES>>>(x, qkv_b, nullptr, 1152, 6, 0);
    attn_kernel<<<NBLK, 384>>>();
    gemm_mm<<<NMT, 256, GSMEM_BYTES>>>(nullptr, proj_b, out, 384, 2, 1);
}

// round 5
// speedup vs baseline: 2.5051x; 1.5303x over previous
#include <cuda_runtime.h>
#include <cuda_fp16.h>
#include <cstdint>

#define NTOK 49
#define NH   12
#define NWIN 64
#define NBLK 8192
#define NROWS (NBLK * NTOK)    /* 401408 = 3136*128 */
#define NMT  3136
#define SCALE 0.17677669529663687f

/* gemm smem (u32 units): A [128 rows][196], B [128 cols][20] */
#define GA_STRIDE 196
#define GB_OFF    25088
#define GSMEM_U32 27648
#define GSMEM_BYTES (GSMEM_U32 * 4)   /* 110592 */

/* attn smem (u32 units): 2 qkv buffers, P, S */
#define ABUF 3252
#define AQ_OFF  0
#define AK_OFF  980
#define AVT_OFF 2100
#define AP_OFF  6504
#define AS_OFF  8808
#define ASMEM_U32 12648
#define ASMEM_BYTES (ASMEM_U32 * 4)   /* 50592 */

/* ---------------- device scratch ---------------- */
__device__ uint32_t g_wq[9 * 12 * 128 * 16];    /* qkv_w fp16 packed  */
__device__ uint32_t g_wp[3 * 12 * 128 * 16];    /* proj_w fp16 packed */
__device__ uint32_t g_q [(size_t)NBLK * NH * 980];
__device__ uint32_t g_k [(size_t)NBLK * NH * 980];
__device__ uint32_t g_vt[(size_t)NBLK * NH * 1152];
__device__ uint32_t g_ob[(size_t)NROWS * 196];
__device__ float    g_bm[NWIN * NH * NTOK * NTOK];

/* ---------------- helpers ---------------- */
__device__ __forceinline__ int SLOT(int p7) { return ((p7 & 3) << 1) | (p7 >> 2); }

__device__ __forceinline__ uint32_t smem_u32(const void* p) {
    uint32_t a;
    asm("{ .reg .u64 t; cvta.to.shared.u64 t, %1; cvt.u32.u64 %0, t; }" : "=r"(a) : "l"(p));
    return a;
}
__device__ __forceinline__ uint32_t h2u(float a, float b) {
    __half2 h = __floats2half2_rn(a, b);
    return *reinterpret_cast<uint32_t*>(&h);
}
__device__ __forceinline__ void cpa16(uint32_t dst, const void* src) {
    asm volatile("cp.async.ca.shared.global [%0], [%1], 16;"
                 :: "r"(dst), "l"(__cvta_generic_to_global(src)));
}
#define CP_COMMIT() asm volatile("cp.async.commit_group;" ::: "memory")
#define CP_WAIT(n)  asm volatile("cp.async.wait_group %0;" :: "n"(n) : "memory")

__device__ __forceinline__ void mma16(float* c, uint32_t a0, uint32_t a1, uint32_t a2,
                                      uint32_t a3, uint32_t b0, uint32_t b1) {
    asm volatile(
        "mma.sync.aligned.m16n8k16.row.col.f32.f16.f16.f32 "
        "{%0,%1,%2,%3},{%4,%5,%6,%7},{%8,%9},{%0,%1,%2,%3};"
        : "+f"(c[0]), "+f"(c[1]), "+f"(c[2]), "+f"(c[3])
        : "r"(a0), "r"(a1), "r"(a2), "r"(a3), "r"(b0), "r"(b1));
}

/* ---------------- prep: pack weights fp16 fragment layout ---------------- */
__global__ void prep_pack(const float* __restrict__ qkv_w, const float* __restrict__ proj_w) {
    int i = blockIdx.x * 256 + threadIdx.x;
    const float* src;
    __half* dst;
    if (i < 1152 * 384) { src = qkv_w; dst = (__half*)g_wq; }
    else { i -= 1152 * 384; src = proj_w; dst = (__half*)g_wp; }
    int c = i / 384, k = i - c * 384;
    int nb = c >> 7, n = c & 127;
    int kc = k >> 5, k5 = k & 31;
    int gl = k5 >> 4, sl = SLOT((k5 >> 1) & 7);
    size_t hid = ((size_t)((nb * 12 + kc) * 128 + n) * 16 + gl * 8 + sl) * 2 + (k5 & 1);
    dst[hid] = __float2half_rn(src[(size_t)c * 384 + k]);
}

__global__ void prep_bm(const float* __restrict__ mask, const float* __restrict__ table,
                        const int* __restrict__ ridx) {
    const int wv = blockIdx.x, h = blockIdx.y;
    float* dst = g_bm + (size_t)(wv * NH + h) * (NTOK * NTOK);
    for (int i = threadIdx.x; i < NTOK * NTOK; i += blockDim.x)
        dst[i] = table[ridx[i] * NH + h] + mask[wv * (NTOK * NTOK) + i];
}

/* ---------------- fp16 mma GEMM: 128 rows x (nbN*128) cols, K=384 ----------------
   mode 0: A=x fp32 (converted), W=g_wq, epilogue -> packed g_q/g_k/g_vt
   mode 1: A=g_ob (raw copy),    W=g_wp, epilogue -> out fp32 + bias        */
__global__ __launch_bounds__(256, 2)
void gemm_mm(const float* __restrict__ Aext, const float* __restrict__ bias,
             float* __restrict__ Cext, int nbN, int mode) {
    extern __shared__ uint32_t sm[];
    const int tid = threadIdx.x, warp = tid >> 5, lane = tid & 31;
    const int lg = lane >> 2, lt = lane & 3;
    const int warpm = warp & 3, warpn = warp >> 2;
    const int mbase = blockIdx.x * 128;
    const uint32_t* W = mode ? g_wp : g_wq;

    /* stage A */
    if (mode == 0) {
        for (int i = tid; i < 12288; i += 256) {
            int r = i / 96, c4 = i - r * 96;
            float4 v = *reinterpret_cast<const float4*>(Aext + (size_t)(mbase + r) * 384 + c4 * 4);
            int g = c4 >> 2, p0 = (c4 << 1) & 7;
            sm[r * GA_STRIDE + g * 8 + SLOT(p0)]     = h2u(v.x, v.y);
            sm[r * GA_STRIDE + g * 8 + SLOT(p0 + 1)] = h2u(v.z, v.w);
        }
    } else {
        const float4* s4 = reinterpret_cast<const float4*>(g_ob + (size_t)mbase * 196);
        float4* d4 = reinterpret_cast<float4*>(sm);
        for (int i = tid; i < 6272; i += 256) d4[i] = s4[i];
    }

    /* precompute rows / (win,t) */
    int rr[4], win[4], tt[4];
    #pragma unroll
    for (int q = 0; q < 4; q++) {
        rr[q] = mbase + warpm * 32 + lg + q * 8;
        win[q] = rr[q] / 49;
        tt[q] = rr[q] - win[q] * 49;
    }

    #pragma unroll 1
    for (int nb = 0; nb < nbN; nb++) {
        float acc[2][8][4];
        #pragma unroll
        for (int a = 0; a < 2; a++)
            #pragma unroll
            for (int f = 0; f < 8; f++)
                #pragma unroll
                for (int c = 0; c < 4; c++) acc[a][f][c] = 0.f;

        const uint32_t* Wnb = W + (size_t)nb * 12 * 2048;
        #pragma unroll 1
        for (int kc = 0; kc < 12; kc++) {
            __syncthreads();
            {
                const float4* s4 = reinterpret_cast<const float4*>(Wnb + kc * 2048);
                #pragma unroll
                for (int i = tid; i < 512; i += 256) {
                    int col = i >> 2, q = i & 3;
                    *reinterpret_cast<float4*>(&sm[GB_OFF + col * 20 + q * 4]) = s4[i];
                }
            }
            __syncthreads();
            #pragma unroll
            for (int gl = 0; gl < 2; gl++) {
                const int ab = (kc * 2 + gl) * 8 + 2 * lt;
                const int R = warpm * 32 + lg;
                uint2 lo0 = *reinterpret_cast<const uint2*>(&sm[R * GA_STRIDE + ab]);
                uint2 hi0 = *reinterpret_cast<const uint2*>(&sm[(R + 8) * GA_STRIDE + ab]);
                uint2 lo1 = *reinterpret_cast<const uint2*>(&sm[(R + 16) * GA_STRIDE + ab]);
                uint2 hi1 = *reinterpret_cast<const uint2*>(&sm[(R + 24) * GA_STRIDE + ab]);
                #pragma unroll
                for (int nf = 0; nf < 8; nf++) {
                    int n = warpn * 64 + nf * 8 + lg;
                    uint2 bb = *reinterpret_cast<const uint2*>(&sm[GB_OFF + n * 20 + gl * 8 + 2 * lt]);
                    mma16(acc[0][nf], lo0.x, hi0.x, lo0.y, hi0.y, bb.x, bb.y);
                    mma16(acc[1][nf], lo1.x, hi1.x, lo1.y, hi1.y, bb.x, bb.y);
                }
            }
        }

        /* epilogue */
        if (mode == 1) {
            #pragma unroll
            for (int nf = 0; nf < 8; nf++) {
                int col = nb * 128 + warpn * 64 + nf * 8 + lt * 2;
                float b0 = __ldg(&bias[col]), b1 = __ldg(&bias[col + 1]);
                #pragma unroll
                for (int mt = 0; mt < 2; mt++) {
                    *reinterpret_cast<float2*>(&Cext[(size_t)rr[mt * 2] * 384 + col]) =
                        make_float2(acc[mt][nf][0] + b0, acc[mt][nf][1] + b1);
                    *reinterpret_cast<float2*>(&Cext[(size_t)rr[mt * 2 + 1] * 384 + col]) =
                        make_float2(acc[mt][nf][2] + b0, acc[mt][nf][3] + b1);
                }
            }
        } else {
            const int part = (nb >= 6) ? 2 : ((nb >= 3) ? 1 : 0);
            const int wcb = (nb - part * 3) * 128 + warpn * 64;
            #pragma unroll
            for (int nf = 0; nf < 8; nf++) {
                int wcol = wcb + nf * 8 + lt * 2;
                int h = wcol >> 5, c32 = wcol & 31;
                int gcol = nb * 128 + warpn * 64 + nf * 8 + lt * 2;
                float b0 = __ldg(&bias[gcol]), b1 = __ldg(&bias[gcol + 1]);
                int gA = c32 >> 4, slA = SLOT((c32 >> 1) & 7);
                #pragma unroll
                for (int q = 0; q < 4; q++) {
                    float v0 = acc[q >> 1][nf][(q & 1) * 2 + 0] + b0;
                    float v1 = acc[q >> 1][nf][(q & 1) * 2 + 1] + b1;
                    size_t hd = (size_t)(win[q] * 12 + h);
                    if (part == 0) {
                        g_q[hd * 980 + tt[q] * 20 + gA * 8 + slA] = h2u(v0 * SCALE, v1 * SCALE);
                    } else if (part == 1) {
                        g_k[hd * 980 + tt[q] * 20 + gA * 8 + slA] = h2u(v0, v1);
                    } else {
                        int gt = tt[q] >> 4, slt = SLOT((tt[q] >> 1) & 7);
                        __half* vtb = (__half*)(g_vt + hd * 1152);
                        int u0 = c32 * 36 + gt * 8 + slt;
                        vtb[u0 * 2 + (tt[q] & 1)] = __float2half_rn(v0);
                        vtb[(u0 + 36) * 2 + (tt[q] & 1)] = __float2half_rn(v1);
                    }
                }
            }
        }
    }
}

/* ---------------- attention (fp16 mma, cp.async staged) ---------------- */
__device__ __forceinline__ void copy_head(uint32_t smb, int b, int h, int buf, int tid) {
    size_t idx = (size_t)(b * 12 + h);
    const float4* sq = reinterpret_cast<const float4*>(g_q + idx * 980);
    const float4* sk = reinterpret_cast<const float4*>(g_k + idx * 980);
    const float4* sv = reinterpret_cast<const float4*>(g_vt + idx * 1152);
    uint32_t d0 = smb + buf * (ABUF * 4);
    for (int i = tid; i < 778; i += 384) {
        if (i < 245)      cpa16(d0 + AQ_OFF * 4 + i * 16, sq + i);
        else if (i < 490) cpa16(d0 + AK_OFF * 4 + (i - 245) * 16, sk + (i - 245));
        else              cpa16(d0 + AVT_OFF * 4 + (i - 490) * 16, sv + (i - 490));
    }
}

__global__ __launch_bounds__(384, 2)
void attn_kernel() {
    extern __shared__ uint32_t sm[];
    float* smf = reinterpret_cast<float*>(sm);
    const uint32_t smb = smem_u32(sm);
    const int b = blockIdx.x;
    const int wi = b & (NWIN - 1);
    const int tid = threadIdx.x, warp = tid >> 5, lane = tid & 31;
    const int lg = lane >> 2, lt = lane & 3;
    const int mt = warp & 3, ng = warp >> 2;
    const int r0 = mt * 16 + lg, r1 = r0 + 8;
    const bool ok0 = r0 < NTOK, ok1 = r1 < NTOK;

    for (int i = tid; i < 2304; i += 384) sm[AP_OFF + i] = 0;   /* zero P */
    copy_head(smb, b, 0, 0, tid);
    CP_COMMIT();

    #pragma unroll 1
    for (int h = 0; h < NH; h++) {
        __syncthreads();
        const int cur = h & 1;
        const uint32_t B0 = cur * ABUF;
        if (h < 11) { copy_head(smb, b, h + 1, cur ^ 1, tid); CP_COMMIT(); CP_WAIT(1); }
        else        { CP_WAIT(0); }
        /* zero pads: K rows 49..55, VT token pads */
        for (int i = tid; i < 140; i += 384) sm[B0 + AK_OFF + 980 + i] = 0;
        if (tid < 224) { int col = tid >> 3, j = tid & 7; if (j < 7) sm[B0 + AVT_OFF + col * 36 + 25 + j] = 0; }
        if (tid >= 224 && tid < 256)
            reinterpret_cast<__half*>(&sm[B0 + AVT_OFF + (tid - 224) * 36 + 24])[1] = __float2half(0.f);
        __syncthreads();

        /* S = q @ k^T (K=32) */
        {
            float sacc[3][4];
            #pragma unroll
            for (int i = 0; i < 3; i++)
                #pragma unroll
                for (int j = 0; j < 4; j++) sacc[i][j] = 0.f;
            const int ntn = (ng == 2) ? 3 : 2;
            const int ntb = (ng == 2) ? 4 : ng * 2;
            #pragma unroll
            for (int g = 0; g < 2; g++) {
                uint2 qlo = make_uint2(0u, 0u), qhi = qlo;
                if (ok0) qlo = *reinterpret_cast<const uint2*>(&sm[B0 + AQ_OFF + r0 * 20 + g * 8 + 2 * lt]);
                if (ok1) qhi = *reinterpret_cast<const uint2*>(&sm[B0 + AQ_OFF + r1 * 20 + g * 8 + 2 * lt]);
                #pragma unroll
                for (int j = 0; j < 3; j++) {
                    if (j < ntn) {
                        int n = (ntb + j) * 8 + lg;
                        uint2 kb = *reinterpret_cast<const uint2*>(&sm[B0 + AK_OFF + n * 20 + g * 8 + 2 * lt]);
                        mma16(sacc[j], qlo.x, qhi.x, qlo.y, qhi.y, kb.x, kb.y);
                    }
                }
            }
            const float* bmh = g_bm + (size_t)(wi * NH + h) * (NTOK * NTOK);
            #pragma unroll
            for (int j = 0; j < 3; j++) {
                if (j < ntn) {
                    #pragma unroll
                    for (int ci = 0; ci < 4; ci++) {
                        int r = (ci & 2) ? r1 : r0;
                        int cc = (ntb + j) * 8 + (lt << 1) + (ci & 1);
                        float v = sacc[j][ci];
                        if (r < NTOK && cc < NTOK) v += bmh[r * NTOK + cc];
                        smf[AS_OFF + r * 60 + cc] = v;
                    }
                }
            }
        }
        __syncthreads();

        /* softmax rows 0..48 -> packed fp16 P */
        for (int r = warp; r < NTOK; r += 12) {
            float v0 = smf[AS_OFF + r * 60 + lane];
            float v1 = (lane + 32 < NTOK) ? smf[AS_OFF + r * 60 + lane + 32] : -1e30f;
            float mx = fmaxf(v0, v1);
            #pragma unroll
            for (int o = 16; o > 0; o >>= 1) mx = fmaxf(mx, __shfl_xor_sync(0xffffffffu, mx, o));
            float e0 = __expf(v0 - mx);
            float e1 = (lane + 32 < NTOK) ? __expf(v1 - mx) : 0.f;
            float s = e0 + e1;
            #pragma unroll
            for (int o = 16; o > 0; o >>= 1) s += __shfl_xor_sync(0xffffffffu, s, o);
            float inv = 1.0f / s;
            int c = lane;
            reinterpret_cast<__half*>(&sm[AP_OFF + r * 36 + (c >> 4) * 8 + SLOT((c >> 1) & 7)])[c & 1] =
                __float2half_rn(e0 * inv);
            int c2 = lane + 32;
            if (c2 < 56) {
                float pv = (c2 < NTOK) ? e1 * inv : 0.f;
                reinterpret_cast<__half*>(&sm[AP_OFF + r * 36 + (c2 >> 4) * 8 + SLOT((c2 >> 1) & 7)])[c2 & 1] =
                    __float2half_rn(pv);
            }
        }
        __syncthreads();

        /* O = P @ V (K=64 padded) -> g_ob packed */
        {
            float oacc[2][4];
            #pragma unroll
            for (int i = 0; i < 2; i++)
                #pragma unroll
                for (int j = 0; j < 4; j++) oacc[i][j] = 0.f;
            const int non = (ng == 2) ? 2 : 1;
            const int nob = (ng == 2) ? 2 : ng;
            #pragma unroll
            for (int g = 0; g < 4; g++) {
                uint2 plo = *reinterpret_cast<const uint2*>(&sm[AP_OFF + r0 * 36 + g * 8 + 2 * lt]);
                uint2 phi = *reinterpret_cast<const uint2*>(&sm[AP_OFF + r1 * 36 + g * 8 + 2 * lt]);
                #pragma unroll
                for (int j = 0; j < 2; j++) {
                    if (j < non) {
                        int n = (nob + j) * 8 + lg;
                        uint2 vb = *reinterpret_cast<const uint2*>(&sm[B0 + AVT_OFF + n * 36 + g * 8 + 2 * lt]);
                        mma16(oacc[j], plo.x, phi.x, plo.y, phi.y, vb.x, vb.y);
                    }
                }
            }
            #pragma unroll
            for (int j = 0; j < 2; j++) {
                if (j < non) {
                    int cc = (nob + j) * 8 + lt * 2;
                    int col = h * 32 + cc;
                    int gA = col >> 4, slA = SLOT((col >> 1) & 7);
                    if (ok0)
                        g_ob[(size_t)(b * NTOK + r0) * 196 + gA * 8 + slA] = h2u(oacc[j][0], oacc[j][1]);
                    if (ok1)
                        g_ob[(size_t)(b * NTOK + r1) * 196 + gA * 8 + slA] = h2u(oacc[j][2], oacc[j][3]);
                }
            }
        }
    }
}

/* ---------------- launcher ---------------- */
extern "C" void kernel_launch(void* const* d_in, const int* in_sizes, int n_in,
                              void* d_out, int out_size) {
    const float* x      = (const float*)d_in[0];
    const float* mask   = (const float*)d_in[1];
    const float* table  = (const float*)d_in[2];
    const float* qkv_w  = (const float*)d_in[3];
    const float* qkv_b  = (const float*)d_in[4];
    const float* proj_w = (const float*)d_in[5];
    const float* proj_b = (const float*)d_in[6];
    const int*   ridx   = (const int*)d_in[7];
    float* out = (float*)d_out;

    cudaFuncSetAttribute(gemm_mm, cudaFuncAttributeMaxDynamicSharedMemorySize, GSMEM_BYTES);
    cudaFuncSetAttribute(attn_kernel, cudaFuncAttributeMaxDynamicSharedMemorySize, ASMEM_BYTES);

    prep_pack<<<2304, 256>>>(qkv_w, proj_w);
    prep_bm<<<dim3(NWIN, NH), 128>>>(mask, table, ridx);
    gemm_mm<<<NMT, 256, GSMEM_BYTES>>>(x, qkv_b, nullptr, 9, 0);
    attn_kernel<<<NBLK, 384, ASMEM_BYTES>>>();
    gemm_mm<<<NMT, 256, GSMEM_BYTES>>>(nullptr, proj_b, out, 3, 1);
}